// round 9
// baseline (speedup 1.0000x reference)
#include <cuda_runtime.h>
#include <math.h>

#define M_BATCH 256
#define R_DIM   1025
#define C_DIM   1024

// Scratch (__device__ globals only — no allocation allowed)
__device__ __align__(16) float g_G[M_BATCH * C_DIM];   // X1 @ mu
__device__ double g_mu2[128];
__device__ double g_lv[4];     // sum exp(lv_in), sum lv_in, sum exp(lv_out), sum lv_out
__device__ int    g_gemm_cnt;
__device__ int    g_dkl_cnt;

// Block partition of the fused kernel (all co-resident: 768 <= 148 * 6)
#define NB_GEMM   128
#define NB_DKL    128
#define NB_STREAM 512
#define NB_TOTAL  (NB_GEMM + NB_DKL + NB_STREAM)

// GEMM tile
#define BM 32
#define BN 64
#define BK 8

__global__ void init_kernel() { g_gemm_cnt = 0; g_dkl_cnt = 0; }

// ---------------------------------------------------------------------------
// Fused kernel:
//   blocks [0,128)    : GEMM  G = X1 @ mu  (sets g_gemm_cnt when done)
//   blocks [128,256)  : D_KL partials; last-to-finish block finalizes D_KL
//   blocks [256,768)  : E-stream, full K, writes final output after spinning
//                       on g_gemm_cnt (gemm finishes ~25us, stream ~160us)
// ---------------------------------------------------------------------------
__global__ __launch_bounds__(128, 6) void fused_kernel(const float* __restrict__ x,
                                                       const float* __restrict__ mu,
                                                       const float* __restrict__ lv_in,
                                                       const float* __restrict__ lv_out,
                                                       const float* __restrict__ E,
                                                       float* __restrict__ out,
                                                       int write_dkl) {
    __shared__ __align__(16) char sh_raw[4416];
    const int bid = blockIdx.x;
    const int t   = threadIdx.x;

    if (bid < NB_GEMM) {
        // ---------------- GEMM: G = X1 @ mu, 32x64 tile ----------------
        float (*As)[33] = reinterpret_cast<float (*)[33]>(sh_raw);          // 1056 B
        float (*Bs)[BN] = reinterpret_cast<float (*)[BN]>(sh_raw + 1056);   // 2048 B

        const int bn0 = (bid & 15) * BN;
        const int bm0 = (bid >> 4) * BM;
        const int tx = t & 15;
        const int ty = t >> 4;

        float c[4][4];
        #pragma unroll
        for (int i = 0; i < 4; i++)
            #pragma unroll
            for (int j = 0; j < 4; j++) c[i][j] = 0.0f;

        for (int k0 = 0; k0 < R_DIM; k0 += BK) {
            #pragma unroll
            for (int p = 0; p < 2; p++) {
                int idx = t + p * 128;
                int kk = idx & 7;
                int m  = idx >> 3;
                int gi = k0 + kk;
                float av = 0.0f;
                if (gi < R_DIM)
                    av = (gi < C_DIM) ? x[(bm0 + m) * C_DIM + gi] : 1.0f;
                As[kk][m] = av;
            }
            #pragma unroll
            for (int p = 0; p < 4; p++) {
                int idx = t + p * 128;
                int n  = idx & 63;
                int kk = idx >> 6;
                int gi = k0 + kk;
                Bs[kk][n] = (gi < R_DIM) ? mu[gi * C_DIM + bn0 + n] : 0.0f;
            }
            __syncthreads();

            #pragma unroll
            for (int kk = 0; kk < BK; kk++) {
                float a[4], bb[4];
                #pragma unroll
                for (int i = 0; i < 4; i++) a[i]  = As[kk][ty * 4 + i];
                #pragma unroll
                for (int j = 0; j < 4; j++) bb[j] = Bs[kk][tx * 4 + j];
                #pragma unroll
                for (int i = 0; i < 4; i++)
                    #pragma unroll
                    for (int j = 0; j < 4; j++)
                        c[i][j] += a[i] * bb[j];
            }
            __syncthreads();
        }

        #pragma unroll
        for (int i = 0; i < 4; i++) {
            int gm = bm0 + ty * 4 + i;
            float4 v = make_float4(c[i][0], c[i][1], c[i][2], c[i][3]);
            *reinterpret_cast<float4*>(&g_G[gm * C_DIM + bn0 + tx * 4]) = v;
        }

        __threadfence();
        __syncthreads();
        if (t == 0) atomicAdd(&g_gemm_cnt, 1);
        return;
    }

    if (bid < NB_GEMM + NB_DKL) {
        // ---------------- D_KL partials + last-block finalize ----------------
        double* red = reinterpret_cast<double*>(sh_raw);  // 128 doubles
        const int db = bid - NB_GEMM;

        // mu^2 over R_DIM*C_DIM = 1,049,600 floats = 262,400 float4s
        const int total4 = (R_DIM * C_DIM) / 4;
        const float4* __restrict__ mu4 = reinterpret_cast<const float4*>(mu);

        float s = 0.0f;
        for (int idx = db * 128 + t; idx < total4; idx += 128 * 128) {
            float4 v = mu4[idx];
            s = fmaf(v.x, v.x, s);
            s = fmaf(v.y, v.y, s);
            s = fmaf(v.z, v.z, s);
            s = fmaf(v.w, v.w, s);
        }
        red[t] = (double)s;
        __syncthreads();
        for (int w = 64; w > 0; w >>= 1) {
            if (t < w) red[t] += red[t + w];
            __syncthreads();
        }
        if (t == 0) g_mu2[db] = red[0];

        if (db == 0) {
            double vals[4] = {0.0, 0.0, 0.0, 0.0};
            for (int i = t; i < R_DIM; i += 128) {
                float l = lv_in[i];
                vals[0] += (double)expf(l);
                vals[1] += (double)l;
            }
            for (int i = t; i < C_DIM; i += 128) {
                float l = lv_out[i];
                vals[2] += (double)expf(l);
                vals[3] += (double)l;
            }
            for (int j = 0; j < 4; j++) {
                __syncthreads();
                red[t] = vals[j];
                __syncthreads();
                for (int w = 64; w > 0; w >>= 1) {
                    if (t < w) red[t] += red[t + w];
                    __syncthreads();
                }
                if (t == 0) g_lv[j] = red[0];
            }
        }

        __threadfence();
        __syncthreads();
        __shared__ int is_last;
        if (t == 0) is_last = (atomicAdd(&g_dkl_cnt, 1) == NB_DKL - 1) ? 1 : 0;
        __syncthreads();

        if (is_last && write_dkl) {
            __threadfence();  // make peers' g_mu2 / g_lv visible
            red[t] = g_mu2[t];
            __syncthreads();
            for (int w = 64; w > 0; w >>= 1) {
                if (t < w) red[t] += red[t + w];
                __syncthreads();
            }
            if (t == 0) {
                double dkl = 0.5 * (g_lv[0] * g_lv[2] + red[0]
                                    - (double)R_DIM * (double)C_DIM
                                    - (double)C_DIM * g_lv[1]
                                    - (double)R_DIM * g_lv[3]);
                out[M_BATCH * C_DIM] = (float)dkl;
            }
        }
        return;
    }

    // ---------------- E-streaming (DRAM-bound), full K per block ----------------
    {
        float* y_sh = reinterpret_cast<float*>(sh_raw);  // R_DIM floats

        const int lin = bid - (NB_GEMM + NB_DKL);
        const int oh = lin & 1;
        const int b  = lin >> 1;

        for (int i = t; i < R_DIM; i += 128) {
            float xv = (i < C_DIM) ? x[b * C_DIM + i] : 1.0f;
            y_sh[i] = xv * expf(0.5f * lv_in[i]);
        }
        __syncthreads();

        const int o = oh * 512 + t * 4;
        const float4* __restrict__ Ep =
            reinterpret_cast<const float4*>(E + (size_t)b * (size_t)(R_DIM * C_DIM) + o);

        float4 sc = make_float4(expf(0.5f * lv_out[o + 0]),
                                expf(0.5f * lv_out[o + 1]),
                                expf(0.5f * lv_out[o + 2]),
                                expf(0.5f * lv_out[o + 3]));

        float4 acc[4];
        #pragma unroll
        for (int r = 0; r < 4; r++) acc[r] = make_float4(0.f, 0.f, 0.f, 0.f);

        const int STR = C_DIM / 4;

        int i = 0;
        for (; i + 16 <= R_DIM; i += 16) {
            float4 e[16];
            #pragma unroll
            for (int r = 0; r < 16; r++)
                e[r] = __ldcs(&Ep[(i + r) * STR]);
            #pragma unroll
            for (int r = 0; r < 16; r++) {
                float yv = y_sh[i + r];
                acc[r & 3].x += yv * e[r].x;
                acc[r & 3].y += yv * e[r].y;
                acc[r & 3].z += yv * e[r].z;
                acc[r & 3].w += yv * e[r].w;
            }
        }
        for (; i < R_DIM; i++) {  // remainder (bias row 1024)
            float yv = y_sh[i];
            float4 e = __ldcs(&Ep[i * STR]);
            acc[0].x += yv * e.x; acc[0].y += yv * e.y;
            acc[0].z += yv * e.z; acc[0].w += yv * e.w;
        }

        float4 r4 = make_float4(acc[0].x + acc[1].x + acc[2].x + acc[3].x,
                                acc[0].y + acc[1].y + acc[2].y + acc[3].y,
                                acc[0].z + acc[1].z + acc[2].z + acc[3].z,
                                acc[0].w + acc[1].w + acc[2].w + acc[3].w);

        // Wait for GEMM blocks (gemm done ~25us into a ~160us stream; all
        // blocks co-resident => spin is safe and essentially free)
        if (t == 0) {
            while (atomicAdd(&g_gemm_cnt, 0) < NB_GEMM) { }
        }
        __syncthreads();
        __threadfence();

        const float4 g = *reinterpret_cast<const float4*>(&g_G[b * C_DIM + o]);
        float4 res = make_float4(g.x + sc.x * r4.x,
                                 g.y + sc.y * r4.y,
                                 g.z + sc.z * r4.z,
                                 g.w + sc.w * r4.w);
        *reinterpret_cast<float4*>(&out[b * C_DIM + o]) = res;
    }
}

// ---------------------------------------------------------------------------
extern "C" void kernel_launch(void* const* d_in, const int* in_sizes, int n_in,
                              void* d_out, int out_size) {
    const float* x      = (const float*)d_in[0];
    const float* mu     = (const float*)d_in[1];
    const float* lv_in  = (const float*)d_in[2];
    const float* lv_out = (const float*)d_in[3];
    const float* E      = (const float*)d_in[4];
    float* out = (float*)d_out;

    init_kernel<<<1, 1>>>();
    fused_kernel<<<NB_TOTAL, 128>>>(x, mu, lv_in, lv_out, E, out,
                                    out_size > M_BATCH * C_DIM ? 1 : 0);
}

// round 10
// speedup vs baseline: 1.0339x; 1.0339x over previous
#include <cuda_runtime.h>
#include <math.h>

#define M_BATCH 256
#define R_DIM   1025
#define C_DIM   1024

// Scratch (__device__ globals only — no allocation allowed)
__device__ __align__(16) float g_G[M_BATCH * C_DIM];   // X1 @ mu
__device__ double g_mu2[128];
__device__ double g_lv[4];     // sum exp(lv_in), sum lv_in, sum exp(lv_out), sum lv_out
__device__ int    g_gemm_cnt;
__device__ int    g_dkl_cnt;

// Block partition of the fused kernel (all co-resident: 768 <= 148 * 6)
#define NB_GEMM   128
#define NB_DKL    128
#define NB_STREAM 512
#define NB_TOTAL  (NB_GEMM + NB_DKL + NB_STREAM)

// GEMM tile
#define BM 32
#define BN 64
#define BK 8

__global__ void init_kernel() { g_gemm_cnt = 0; g_dkl_cnt = 0; }

// ---------------------------------------------------------------------------
// Fused kernel (best verified config: R5/R8, 163.6us @ 84% DRAM):
//   blocks [0,128)    : GEMM  G = X1 @ mu  (sets g_gemm_cnt when done)
//   blocks [128,256)  : D_KL partials (scalar mu loads — deliberately sparse
//                       so they don't contend with stream L1tex traffic);
//                       last-to-finish block finalizes D_KL
//   blocks [256,768)  : E-stream, full K, 16-deep LDG.128 batches, __ldcs;
//                       writes final output after spinning on g_gemm_cnt
// ---------------------------------------------------------------------------
__global__ __launch_bounds__(128, 6) void fused_kernel(const float* __restrict__ x,
                                                       const float* __restrict__ mu,
                                                       const float* __restrict__ lv_in,
                                                       const float* __restrict__ lv_out,
                                                       const float* __restrict__ E,
                                                       float* __restrict__ out,
                                                       int write_dkl) {
    __shared__ __align__(16) char sh_raw[4416];
    const int bid = blockIdx.x;
    const int t   = threadIdx.x;

    if (bid < NB_GEMM) {
        // ---------------- GEMM: G = X1 @ mu, 32x64 tile ----------------
        float (*As)[33] = reinterpret_cast<float (*)[33]>(sh_raw);          // 1056 B
        float (*Bs)[BN] = reinterpret_cast<float (*)[BN]>(sh_raw + 1056);   // 2048 B

        const int bn0 = (bid & 15) * BN;
        const int bm0 = (bid >> 4) * BM;
        const int tx = t & 15;
        const int ty = t >> 4;

        float c[4][4];
        #pragma unroll
        for (int i = 0; i < 4; i++)
            #pragma unroll
            for (int j = 0; j < 4; j++) c[i][j] = 0.0f;

        for (int k0 = 0; k0 < R_DIM; k0 += BK) {
            #pragma unroll
            for (int p = 0; p < 2; p++) {
                int idx = t + p * 128;
                int kk = idx & 7;
                int m  = idx >> 3;
                int gi = k0 + kk;
                float av = 0.0f;
                if (gi < R_DIM)
                    av = (gi < C_DIM) ? x[(bm0 + m) * C_DIM + gi] : 1.0f;
                As[kk][m] = av;
            }
            #pragma unroll
            for (int p = 0; p < 4; p++) {
                int idx = t + p * 128;
                int n  = idx & 63;
                int kk = idx >> 6;
                int gi = k0 + kk;
                Bs[kk][n] = (gi < R_DIM) ? mu[gi * C_DIM + bn0 + n] : 0.0f;
            }
            __syncthreads();

            #pragma unroll
            for (int kk = 0; kk < BK; kk++) {
                float a[4], bb[4];
                #pragma unroll
                for (int i = 0; i < 4; i++) a[i]  = As[kk][ty * 4 + i];
                #pragma unroll
                for (int j = 0; j < 4; j++) bb[j] = Bs[kk][tx * 4 + j];
                #pragma unroll
                for (int i = 0; i < 4; i++)
                    #pragma unroll
                    for (int j = 0; j < 4; j++)
                        c[i][j] += a[i] * bb[j];
            }
            __syncthreads();
        }

        #pragma unroll
        for (int i = 0; i < 4; i++) {
            int gm = bm0 + ty * 4 + i;
            float4 v = make_float4(c[i][0], c[i][1], c[i][2], c[i][3]);
            *reinterpret_cast<float4*>(&g_G[gm * C_DIM + bn0 + tx * 4]) = v;
        }

        __threadfence();
        __syncthreads();
        if (t == 0) atomicAdd(&g_gemm_cnt, 1);
        return;
    }

    if (bid < NB_GEMM + NB_DKL) {
        // ---------------- D_KL partials + last-block finalize ----------------
        double* red = reinterpret_cast<double*>(sh_raw);  // 128 doubles
        const int db = bid - NB_GEMM;
        const int total = R_DIM * C_DIM;

        float s = 0.0f;
        for (int idx = db * 128 + t; idx < total; idx += 128 * 128) {
            float v = mu[idx];
            s = fmaf(v, v, s);
        }
        red[t] = (double)s;
        __syncthreads();
        for (int w = 64; w > 0; w >>= 1) {
            if (t < w) red[t] += red[t + w];
            __syncthreads();
        }
        if (t == 0) g_mu2[db] = red[0];

        if (db == 0) {
            double vals[4] = {0.0, 0.0, 0.0, 0.0};
            for (int i = t; i < R_DIM; i += 128) {
                float l = lv_in[i];
                vals[0] += (double)expf(l);
                vals[1] += (double)l;
            }
            for (int i = t; i < C_DIM; i += 128) {
                float l = lv_out[i];
                vals[2] += (double)expf(l);
                vals[3] += (double)l;
            }
            for (int j = 0; j < 4; j++) {
                __syncthreads();
                red[t] = vals[j];
                __syncthreads();
                for (int w = 64; w > 0; w >>= 1) {
                    if (t < w) red[t] += red[t + w];
                    __syncthreads();
                }
                if (t == 0) g_lv[j] = red[0];
            }
        }

        __threadfence();
        __syncthreads();
        __shared__ int is_last;
        if (t == 0) is_last = (atomicAdd(&g_dkl_cnt, 1) == NB_DKL - 1) ? 1 : 0;
        __syncthreads();

        if (is_last && write_dkl) {
            __threadfence();  // make peers' g_mu2 / g_lv visible
            red[t] = g_mu2[t];
            __syncthreads();
            for (int w = 64; w > 0; w >>= 1) {
                if (t < w) red[t] += red[t + w];
                __syncthreads();
            }
            if (t == 0) {
                double dkl = 0.5 * (g_lv[0] * g_lv[2] + red[0]
                                    - (double)R_DIM * (double)C_DIM
                                    - (double)C_DIM * g_lv[1]
                                    - (double)R_DIM * g_lv[3]);
                out[M_BATCH * C_DIM] = (float)dkl;
            }
        }
        return;
    }

    // ---------------- E-streaming (DRAM-bound), full K per block ----------------
    {
        float* y_sh = reinterpret_cast<float*>(sh_raw);  // R_DIM floats

        const int lin = bid - (NB_GEMM + NB_DKL);
        const int oh = lin & 1;
        const int b  = lin >> 1;

        for (int i = t; i < R_DIM; i += 128) {
            float xv = (i < C_DIM) ? x[b * C_DIM + i] : 1.0f;
            y_sh[i] = xv * expf(0.5f * lv_in[i]);
        }
        __syncthreads();

        const int o = oh * 512 + t * 4;
        const float4* __restrict__ Ep =
            reinterpret_cast<const float4*>(E + (size_t)b * (size_t)(R_DIM * C_DIM) + o);

        float4 sc = make_float4(expf(0.5f * lv_out[o + 0]),
                                expf(0.5f * lv_out[o + 1]),
                                expf(0.5f * lv_out[o + 2]),
                                expf(0.5f * lv_out[o + 3]));

        float4 acc[4];
        #pragma unroll
        for (int r = 0; r < 4; r++) acc[r] = make_float4(0.f, 0.f, 0.f, 0.f);

        const int STR = C_DIM / 4;

        int i = 0;
        for (; i + 16 <= R_DIM; i += 16) {
            float4 e[16];
            #pragma unroll
            for (int r = 0; r < 16; r++)
                e[r] = __ldcs(&Ep[(i + r) * STR]);
            #pragma unroll
            for (int r = 0; r < 16; r++) {
                float yv = y_sh[i + r];
                acc[r & 3].x += yv * e[r].x;
                acc[r & 3].y += yv * e[r].y;
                acc[r & 3].z += yv * e[r].z;
                acc[r & 3].w += yv * e[r].w;
            }
        }
        for (; i < R_DIM; i++) {  // remainder (bias row 1024)
            float yv = y_sh[i];
            float4 e = __ldcs(&Ep[i * STR]);
            acc[0].x += yv * e.x; acc[0].y += yv * e.y;
            acc[0].z += yv * e.z; acc[0].w += yv * e.w;
        }

        float4 r4 = make_float4(acc[0].x + acc[1].x + acc[2].x + acc[3].x,
                                acc[0].y + acc[1].y + acc[2].y + acc[3].y,
                                acc[0].z + acc[1].z + acc[2].z + acc[3].z,
                                acc[0].w + acc[1].w + acc[2].w + acc[3].w);

        // Wait for GEMM blocks (gemm done ~25us into a ~160us stream; all
        // blocks co-resident => spin is safe and essentially free)
        if (t == 0) {
            while (atomicAdd(&g_gemm_cnt, 0) < NB_GEMM) { }
        }
        __syncthreads();
        __threadfence();

        const float4 g = *reinterpret_cast<const float4*>(&g_G[b * C_DIM + o]);
        float4 res = make_float4(g.x + sc.x * r4.x,
                                 g.y + sc.y * r4.y,
                                 g.z + sc.z * r4.z,
                                 g.w + sc.w * r4.w);
        *reinterpret_cast<float4*>(&out[b * C_DIM + o]) = res;
    }
}

// ---------------------------------------------------------------------------
extern "C" void kernel_launch(void* const* d_in, const int* in_sizes, int n_in,
                              void* d_out, int out_size) {
    const float* x      = (const float*)d_in[0];
    const float* mu     = (const float*)d_in[1];
    const float* lv_in  = (const float*)d_in[2];
    const float* lv_out = (const float*)d_in[3];
    const float* E      = (const float*)d_in[4];
    float* out = (float*)d_out;

    init_kernel<<<1, 1>>>();
    fused_kernel<<<NB_TOTAL, 128>>>(x, mu, lv_in, lv_out, E, out,
                                    out_size > M_BATCH * C_DIM ? 1 : 0);
}

// round 11
// speedup vs baseline: 1.0489x; 1.0146x over previous
#include <cuda_runtime.h>
#include <math.h>

#define M_BATCH 256
#define R_DIM   1025
#define C_DIM   1024

// Scratch (__device__ globals only — no allocation allowed)
__device__ __align__(16) float g_G[M_BATCH * C_DIM];   // X1 @ mu
__device__ double g_mu2[128];
__device__ double g_lv[4];     // sum exp(lv_in), sum lv_in, sum exp(lv_out), sum lv_out
__device__ int    g_gemm_cnt;
__device__ int    g_dkl_cnt;

// Block partition of the fused kernel (all co-resident: 768 <= 148 * 6)
#define NB_GEMM   128
#define NB_DKL    128
#define NB_STREAM 512
#define NB_TOTAL  (NB_GEMM + NB_DKL + NB_STREAM)

// GEMM tile
#define BM 32
#define BN 64
#define BK 8

__global__ void init_kernel() { g_gemm_cnt = 0; g_dkl_cnt = 0; }

// ---------------------------------------------------------------------------
// Fused kernel (converged config, 162.6us @ ~84% DRAM, ~1.4% off the
// demonstrated streaming ceiling for this access pattern):
//   blocks [0,128)    : GEMM  G = X1 @ mu  (sets g_gemm_cnt when done)
//   blocks [128,256)  : D_KL partials (scalar mu loads — deliberately sparse
//                       so they don't contend with stream L1tex traffic);
//                       last-to-finish block finalizes D_KL
//   blocks [256,768)  : E-stream, full K, 16-deep LDG.128 batches, __ldcs;
//                       writes final output after spinning on g_gemm_cnt
// ---------------------------------------------------------------------------
__global__ __launch_bounds__(128, 6) void fused_kernel(const float* __restrict__ x,
                                                       const float* __restrict__ mu,
                                                       const float* __restrict__ lv_in,
                                                       const float* __restrict__ lv_out,
                                                       const float* __restrict__ E,
                                                       float* __restrict__ out,
                                                       int write_dkl) {
    __shared__ __align__(16) char sh_raw[4416];
    const int bid = blockIdx.x;
    const int t   = threadIdx.x;

    if (bid < NB_GEMM) {
        // ---------------- GEMM: G = X1 @ mu, 32x64 tile ----------------
        float (*As)[33] = reinterpret_cast<float (*)[33]>(sh_raw);          // 1056 B
        float (*Bs)[BN] = reinterpret_cast<float (*)[BN]>(sh_raw + 1056);   // 2048 B

        const int bn0 = (bid & 15) * BN;
        const int bm0 = (bid >> 4) * BM;
        const int tx = t & 15;
        const int ty = t >> 4;

        float c[4][4];
        #pragma unroll
        for (int i = 0; i < 4; i++)
            #pragma unroll
            for (int j = 0; j < 4; j++) c[i][j] = 0.0f;

        for (int k0 = 0; k0 < R_DIM; k0 += BK) {
            #pragma unroll
            for (int p = 0; p < 2; p++) {
                int idx = t + p * 128;
                int kk = idx & 7;
                int m  = idx >> 3;
                int gi = k0 + kk;
                float av = 0.0f;
                if (gi < R_DIM)
                    av = (gi < C_DIM) ? x[(bm0 + m) * C_DIM + gi] : 1.0f;
                As[kk][m] = av;
            }
            #pragma unroll
            for (int p = 0; p < 4; p++) {
                int idx = t + p * 128;
                int n  = idx & 63;
                int kk = idx >> 6;
                int gi = k0 + kk;
                Bs[kk][n] = (gi < R_DIM) ? mu[gi * C_DIM + bn0 + n] : 0.0f;
            }
            __syncthreads();

            #pragma unroll
            for (int kk = 0; kk < BK; kk++) {
                float a[4], bb[4];
                #pragma unroll
                for (int i = 0; i < 4; i++) a[i]  = As[kk][ty * 4 + i];
                #pragma unroll
                for (int j = 0; j < 4; j++) bb[j] = Bs[kk][tx * 4 + j];
                #pragma unroll
                for (int i = 0; i < 4; i++)
                    #pragma unroll
                    for (int j = 0; j < 4; j++)
                        c[i][j] += a[i] * bb[j];
            }
            __syncthreads();
        }

        #pragma unroll
        for (int i = 0; i < 4; i++) {
            int gm = bm0 + ty * 4 + i;
            float4 v = make_float4(c[i][0], c[i][1], c[i][2], c[i][3]);
            *reinterpret_cast<float4*>(&g_G[gm * C_DIM + bn0 + tx * 4]) = v;
        }

        __threadfence();
        __syncthreads();
        if (t == 0) atomicAdd(&g_gemm_cnt, 1);
        return;
    }

    if (bid < NB_GEMM + NB_DKL) {
        // ---------------- D_KL partials + last-block finalize ----------------
        double* red = reinterpret_cast<double*>(sh_raw);  // 128 doubles
        const int db = bid - NB_GEMM;
        const int total = R_DIM * C_DIM;

        float s = 0.0f;
        for (int idx = db * 128 + t; idx < total; idx += 128 * 128) {
            float v = mu[idx];
            s = fmaf(v, v, s);
        }
        red[t] = (double)s;
        __syncthreads();
        for (int w = 64; w > 0; w >>= 1) {
            if (t < w) red[t] += red[t + w];
            __syncthreads();
        }
        if (t == 0) g_mu2[db] = red[0];

        if (db == 0) {
            double vals[4] = {0.0, 0.0, 0.0, 0.0};
            for (int i = t; i < R_DIM; i += 128) {
                float l = lv_in[i];
                vals[0] += (double)expf(l);
                vals[1] += (double)l;
            }
            for (int i = t; i < C_DIM; i += 128) {
                float l = lv_out[i];
                vals[2] += (double)expf(l);
                vals[3] += (double)l;
            }
            for (int j = 0; j < 4; j++) {
                __syncthreads();
                red[t] = vals[j];
                __syncthreads();
                for (int w = 64; w > 0; w >>= 1) {
                    if (t < w) red[t] += red[t + w];
                    __syncthreads();
                }
                if (t == 0) g_lv[j] = red[0];
            }
        }

        __threadfence();
        __syncthreads();
        __shared__ int is_last;
        if (t == 0) is_last = (atomicAdd(&g_dkl_cnt, 1) == NB_DKL - 1) ? 1 : 0;
        __syncthreads();

        if (is_last && write_dkl) {
            __threadfence();  // make peers' g_mu2 / g_lv visible
            red[t] = g_mu2[t];
            __syncthreads();
            for (int w = 64; w > 0; w >>= 1) {
                if (t < w) red[t] += red[t + w];
                __syncthreads();
            }
            if (t == 0) {
                double dkl = 0.5 * (g_lv[0] * g_lv[2] + red[0]
                                    - (double)R_DIM * (double)C_DIM
                                    - (double)C_DIM * g_lv[1]
                                    - (double)R_DIM * g_lv[3]);
                out[M_BATCH * C_DIM] = (float)dkl;
            }
        }
        return;
    }

    // ---------------- E-streaming (DRAM-bound), full K per block ----------------
    {
        float* y_sh = reinterpret_cast<float*>(sh_raw);  // R_DIM floats

        const int lin = bid - (NB_GEMM + NB_DKL);
        const int oh = lin & 1;
        const int b  = lin >> 1;

        for (int i = t; i < R_DIM; i += 128) {
            float xv = (i < C_DIM) ? x[b * C_DIM + i] : 1.0f;
            y_sh[i] = xv * expf(0.5f * lv_in[i]);
        }
        __syncthreads();

        const int o = oh * 512 + t * 4;
        const float4* __restrict__ Ep =
            reinterpret_cast<const float4*>(E + (size_t)b * (size_t)(R_DIM * C_DIM) + o);

        float4 sc = make_float4(expf(0.5f * lv_out[o + 0]),
                                expf(0.5f * lv_out[o + 1]),
                                expf(0.5f * lv_out[o + 2]),
                                expf(0.5f * lv_out[o + 3]));

        float4 acc[4];
        #pragma unroll
        for (int r = 0; r < 4; r++) acc[r] = make_float4(0.f, 0.f, 0.f, 0.f);

        const int STR = C_DIM / 4;

        int i = 0;
        for (; i + 16 <= R_DIM; i += 16) {
            float4 e[16];
            #pragma unroll
            for (int r = 0; r < 16; r++)
                e[r] = __ldcs(&Ep[(i + r) * STR]);
            #pragma unroll
            for (int r = 0; r < 16; r++) {
                float yv = y_sh[i + r];
                acc[r & 3].x += yv * e[r].x;
                acc[r & 3].y += yv * e[r].y;
                acc[r & 3].z += yv * e[r].z;
                acc[r & 3].w += yv * e[r].w;
            }
        }
        for (; i < R_DIM; i++) {  // remainder (bias row 1024)
            float yv = y_sh[i];
            float4 e = __ldcs(&Ep[i * STR]);
            acc[0].x += yv * e.x; acc[0].y += yv * e.y;
            acc[0].z += yv * e.z; acc[0].w += yv * e.w;
        }

        float4 r4 = make_float4(acc[0].x + acc[1].x + acc[2].x + acc[3].x,
                                acc[0].y + acc[1].y + acc[2].y + acc[3].y,
                                acc[0].z + acc[1].z + acc[2].z + acc[3].z,
                                acc[0].w + acc[1].w + acc[2].w + acc[3].w);

        // Wait for GEMM blocks (gemm done ~25us into a ~160us stream; all
        // blocks co-resident => spin is safe and essentially free)
        if (t == 0) {
            while (atomicAdd(&g_gemm_cnt, 0) < NB_GEMM) { }
        }
        __syncthreads();
        __threadfence();

        const float4 g = *reinterpret_cast<const float4*>(&g_G[b * C_DIM + o]);
        float4 res = make_float4(g.x + sc.x * r4.x,
                                 g.y + sc.y * r4.y,
                                 g.z + sc.z * r4.z,
                                 g.w + sc.w * r4.w);
        *reinterpret_cast<float4*>(&out[b * C_DIM + o]) = res;
    }
}

// ---------------------------------------------------------------------------
extern "C" void kernel_launch(void* const* d_in, const int* in_sizes, int n_in,
                              void* d_out, int out_size) {
    const float* x      = (const float*)d_in[0];
    const float* mu     = (const float*)d_in[1];
    const float* lv_in  = (const float*)d_in[2];
    const float* lv_out = (const float*)d_in[3];
    const float* E      = (const float*)d_in[4];
    float* out = (float*)d_out;

    init_kernel<<<1, 1>>>();
    fused_kernel<<<NB_TOTAL, 128>>>(x, mu, lv_in, lv_out, E, out,
                                    out_size > M_BATCH * C_DIM ? 1 : 0);
}

// round 12
// speedup vs baseline: 1.0604x; 1.0109x over previous
#include <cuda_runtime.h>
#include <math.h>

#define M_BATCH 256
#define R_DIM   1025
#define C_DIM   1024

// Scratch (__device__ globals only — no allocation allowed)
__device__ __align__(16) float g_G[M_BATCH * C_DIM];   // X1 @ mu
__device__ double g_mu2[128];
__device__ double g_lv[4];     // sum exp(lv_in), sum lv_in, sum exp(lv_out), sum lv_out
__device__ int    g_gemm_cnt;
__device__ int    g_dkl_cnt;

// Block partition of the fused kernel (all co-resident: 768 <= 148 * 6)
#define NB_GEMM   128
#define NB_DKL    128
#define NB_STREAM 512
#define NB_TOTAL  (NB_GEMM + NB_DKL + NB_STREAM)

// GEMM tile
#define BM 32
#define BN 64
#define BK 8

__global__ void init_kernel() { g_gemm_cnt = 0; g_dkl_cnt = 0; }

// ---------------------------------------------------------------------------
// Fused kernel (converged config, ~160us @ ~85% DRAM, at the demonstrated
// streaming ceiling for this access pattern):
//   blocks [0,128)    : GEMM  G = X1 @ mu  (sets g_gemm_cnt when done)
//   blocks [128,256)  : D_KL partials (scalar mu loads — deliberately sparse
//                       so they don't contend with stream L1tex traffic);
//                       last-to-finish block finalizes D_KL
//   blocks [256,768)  : E-stream, full K, 16-deep LDG.128 batches, __ldcs;
//                       writes final output after spinning on g_gemm_cnt
// ---------------------------------------------------------------------------
__global__ __launch_bounds__(128, 6) void fused_kernel(const float* __restrict__ x,
                                                       const float* __restrict__ mu,
                                                       const float* __restrict__ lv_in,
                                                       const float* __restrict__ lv_out,
                                                       const float* __restrict__ E,
                                                       float* __restrict__ out,
                                                       int write_dkl) {
    __shared__ __align__(16) char sh_raw[4416];
    const int bid = blockIdx.x;
    const int t   = threadIdx.x;

    if (bid < NB_GEMM) {
        // ---------------- GEMM: G = X1 @ mu, 32x64 tile ----------------
        float (*As)[33] = reinterpret_cast<float (*)[33]>(sh_raw);          // 1056 B
        float (*Bs)[BN] = reinterpret_cast<float (*)[BN]>(sh_raw + 1056);   // 2048 B

        const int bn0 = (bid & 15) * BN;
        const int bm0 = (bid >> 4) * BM;
        const int tx = t & 15;
        const int ty = t >> 4;

        float c[4][4];
        #pragma unroll
        for (int i = 0; i < 4; i++)
            #pragma unroll
            for (int j = 0; j < 4; j++) c[i][j] = 0.0f;

        for (int k0 = 0; k0 < R_DIM; k0 += BK) {
            #pragma unroll
            for (int p = 0; p < 2; p++) {
                int idx = t + p * 128;
                int kk = idx & 7;
                int m  = idx >> 3;
                int gi = k0 + kk;
                float av = 0.0f;
                if (gi < R_DIM)
                    av = (gi < C_DIM) ? x[(bm0 + m) * C_DIM + gi] : 1.0f;
                As[kk][m] = av;
            }
            #pragma unroll
            for (int p = 0; p < 4; p++) {
                int idx = t + p * 128;
                int n  = idx & 63;
                int kk = idx >> 6;
                int gi = k0 + kk;
                Bs[kk][n] = (gi < R_DIM) ? mu[gi * C_DIM + bn0 + n] : 0.0f;
            }
            __syncthreads();

            #pragma unroll
            for (int kk = 0; kk < BK; kk++) {
                float a[4], bb[4];
                #pragma unroll
                for (int i = 0; i < 4; i++) a[i]  = As[kk][ty * 4 + i];
                #pragma unroll
                for (int j = 0; j < 4; j++) bb[j] = Bs[kk][tx * 4 + j];
                #pragma unroll
                for (int i = 0; i < 4; i++)
                    #pragma unroll
                    for (int j = 0; j < 4; j++)
                        c[i][j] += a[i] * bb[j];
            }
            __syncthreads();
        }

        #pragma unroll
        for (int i = 0; i < 4; i++) {
            int gm = bm0 + ty * 4 + i;
            float4 v = make_float4(c[i][0], c[i][1], c[i][2], c[i][3]);
            *reinterpret_cast<float4*>(&g_G[gm * C_DIM + bn0 + tx * 4]) = v;
        }

        __threadfence();
        __syncthreads();
        if (t == 0) atomicAdd(&g_gemm_cnt, 1);
        return;
    }

    if (bid < NB_GEMM + NB_DKL) {
        // ---------------- D_KL partials + last-block finalize ----------------
        double* red = reinterpret_cast<double*>(sh_raw);  // 128 doubles
        const int db = bid - NB_GEMM;
        const int total = R_DIM * C_DIM;

        float s = 0.0f;
        for (int idx = db * 128 + t; idx < total; idx += 128 * 128) {
            float v = mu[idx];
            s = fmaf(v, v, s);
        }
        red[t] = (double)s;
        __syncthreads();
        for (int w = 64; w > 0; w >>= 1) {
            if (t < w) red[t] += red[t + w];
            __syncthreads();
        }
        if (t == 0) g_mu2[db] = red[0];

        if (db == 0) {
            double vals[4] = {0.0, 0.0, 0.0, 0.0};
            for (int i = t; i < R_DIM; i += 128) {
                float l = lv_in[i];
                vals[0] += (double)expf(l);
                vals[1] += (double)l;
            }
            for (int i = t; i < C_DIM; i += 128) {
                float l = lv_out[i];
                vals[2] += (double)expf(l);
                vals[3] += (double)l;
            }
            for (int j = 0; j < 4; j++) {
                __syncthreads();
                red[t] = vals[j];
                __syncthreads();
                for (int w = 64; w > 0; w >>= 1) {
                    if (t < w) red[t] += red[t + w];
                    __syncthreads();
                }
                if (t == 0) g_lv[j] = red[0];
            }
        }

        __threadfence();
        __syncthreads();
        __shared__ int is_last;
        if (t == 0) is_last = (atomicAdd(&g_dkl_cnt, 1) == NB_DKL - 1) ? 1 : 0;
        __syncthreads();

        if (is_last && write_dkl) {
            __threadfence();  // make peers' g_mu2 / g_lv visible
            red[t] = g_mu2[t];
            __syncthreads();
            for (int w = 64; w > 0; w >>= 1) {
                if (t < w) red[t] += red[t + w];
                __syncthreads();
            }
            if (t == 0) {
                double dkl = 0.5 * (g_lv[0] * g_lv[2] + red[0]
                                    - (double)R_DIM * (double)C_DIM
                                    - (double)C_DIM * g_lv[1]
                                    - (double)R_DIM * g_lv[3]);
                out[M_BATCH * C_DIM] = (float)dkl;
            }
        }
        return;
    }

    // ---------------- E-streaming (DRAM-bound), full K per block ----------------
    {
        float* y_sh = reinterpret_cast<float*>(sh_raw);  // R_DIM floats

        const int lin = bid - (NB_GEMM + NB_DKL);
        const int oh = lin & 1;
        const int b  = lin >> 1;

        for (int i = t; i < R_DIM; i += 128) {
            float xv = (i < C_DIM) ? x[b * C_DIM + i] : 1.0f;
            y_sh[i] = xv * expf(0.5f * lv_in[i]);
        }
        __syncthreads();

        const int o = oh * 512 + t * 4;
        const float4* __restrict__ Ep =
            reinterpret_cast<const float4*>(E + (size_t)b * (size_t)(R_DIM * C_DIM) + o);

        float4 sc = make_float4(expf(0.5f * lv_out[o + 0]),
                                expf(0.5f * lv_out[o + 1]),
                                expf(0.5f * lv_out[o + 2]),
                                expf(0.5f * lv_out[o + 3]));

        float4 acc[4];
        #pragma unroll
        for (int r = 0; r < 4; r++) acc[r] = make_float4(0.f, 0.f, 0.f, 0.f);

        const int STR = C_DIM / 4;

        int i = 0;
        for (; i + 16 <= R_DIM; i += 16) {
            float4 e[16];
            #pragma unroll
            for (int r = 0; r < 16; r++)
                e[r] = __ldcs(&Ep[(i + r) * STR]);
            #pragma unroll
            for (int r = 0; r < 16; r++) {
                float yv = y_sh[i + r];
                acc[r & 3].x += yv * e[r].x;
                acc[r & 3].y += yv * e[r].y;
                acc[r & 3].z += yv * e[r].z;
                acc[r & 3].w += yv * e[r].w;
            }
        }
        for (; i < R_DIM; i++) {  // remainder (bias row 1024)
            float yv = y_sh[i];
            float4 e = __ldcs(&Ep[i * STR]);
            acc[0].x += yv * e.x; acc[0].y += yv * e.y;
            acc[0].z += yv * e.z; acc[0].w += yv * e.w;
        }

        float4 r4 = make_float4(acc[0].x + acc[1].x + acc[2].x + acc[3].x,
                                acc[0].y + acc[1].y + acc[2].y + acc[3].y,
                                acc[0].z + acc[1].z + acc[2].z + acc[3].z,
                                acc[0].w + acc[1].w + acc[2].w + acc[3].w);

        // Wait for GEMM blocks (gemm done ~25us into a ~160us stream; all
        // blocks co-resident => spin is safe and essentially free)
        if (t == 0) {
            while (atomicAdd(&g_gemm_cnt, 0) < NB_GEMM) { }
        }
        __syncthreads();
        __threadfence();

        const float4 g = *reinterpret_cast<const float4*>(&g_G[b * C_DIM + o]);
        float4 res = make_float4(g.x + sc.x * r4.x,
                                 g.y + sc.y * r4.y,
                                 g.z + sc.z * r4.z,
                                 g.w + sc.w * r4.w);
        *reinterpret_cast<float4*>(&out[b * C_DIM + o]) = res;
    }
}

// ---------------------------------------------------------------------------
extern "C" void kernel_launch(void* const* d_in, const int* in_sizes, int n_in,
                              void* d_out, int out_size) {
    const float* x      = (const float*)d_in[0];
    const float* mu     = (const float*)d_in[1];
    const float* lv_in  = (const float*)d_in[2];
    const float* lv_out = (const float*)d_in[3];
    const float* E      = (const float*)d_in[4];
    float* out = (float*)d_out;

    init_kernel<<<1, 1>>>();
    fused_kernel<<<NB_TOTAL, 128>>>(x, mu, lv_in, lv_out, E, out,
                                    out_size > M_BATCH * C_DIM ? 1 : 0);
}